// round 7
// baseline (speedup 1.0000x reference)
#include <cuda_runtime.h>
#include <cstdint>

#define BB 32
#define TT 2000
#define HH 512
#define LL 256
#define THRESH 0.95f

// Scratch (allocation-free rule: __device__ globals)
__device__ float g_scale[BB];          // per-batch alpha rescale factor
__device__ uint2 g_rec[BB * LL];       // [b][k] fire record: {t, bits(cur)}
__device__ int   g_nfires[BB];
__device__ uint2 g_dummy[BB];          // branch-free sink for non-fire stores

// ---------------------------------------------------------------------------
// Kernel A: per-batch alpha sum (fp64, correctly rounded) + exact sequential
// CIF scan. 1 block, 1024 threads: warp w reduces batch w; then warp 0 runs
// all 32 batch scans SIMD (lane = batch).
// Inner loop is fully branch-free: the only store is one STG.64 fire record
// per step, routed to a per-lane dummy slot when not firing. Interior frame
// weights (= alphas*scale) are NOT stored; the gather recomputes them with
// the identical fp32 multiply.
// ---------------------------------------------------------------------------
__global__ void __launch_bounds__(1024, 1)
cif_scan_kernel(const float* __restrict__ alphas, const int* __restrict__ tlen) {
    const int w    = threadIdx.x >> 5;
    const int lane = threadIdx.x & 31;
    __shared__ float s_scale[BB];

    // Phase 1: warp w sums alphas of batch w in double (kept identical to the
    // passing R5/R6 reduction — do not perturb the rounding).
    double s = 0.0;
    const float* ap = alphas + w * TT;
    for (int t = lane; t < TT; t += 32) s += (double)ap[t];
    #pragma unroll
    for (int off = 16; off; off >>= 1) s += __shfl_down_sync(0xffffffffu, s, off);
    if (lane == 0) {
        float sumf = (float)s;                 // fp32 sum (closest to XLA's)
        float sc = (float)tlen[w] / sumf;      // matches ref: num / sum (fp32 div)
        s_scale[w] = sc;
        g_scale[w] = sc;
    }
    __syncthreads();

    // Phase 2: warp 0, lane = batch, exact sequential recurrence.
    if (threadIdx.x < 32) {
        const int b = threadIdx.x;
        const float scale = s_scale[b];
        // Row is 8000 B from 16B-aligned base -> float4-safe; TT % 8 == 0.
        const float4* a4 = (const float4*)(alphas + b * TT);
        uint2* __restrict__ recp = g_rec + b * LL;
        uint2* __restrict__ dump = g_dummy + b;

        float I = 0.0f;
        int   n = 0;

        float4 p = a4[0];
        float4 q = a4[1];
        for (int t0 = 0; t0 < TT; t0 += 8) {
            float4 pn, qn;
            if (t0 + 8 < TT) {                 // prefetch next block
                pn = a4[(t0 >> 2) + 2];
                qn = a4[(t0 >> 2) + 3];
            }
            float ab[8] = {p.x, p.y, p.z, p.w, q.x, q.y, q.z, q.w};
            #pragma unroll
            for (int u = 0; u < 8; ++u) {
                const int t = t0 + u;
                float a = ab[u] * scale;       // ref: alphas * scale (fp32 mul)
                float d = 1.0f - I;            // dist_completion (old integrate)
                I = I + a;
                bool fire = (I >= THRESH);
                float cur = fire ? d : a;
                // Branch-free fire record (STG.64, address-selected)
                uint2 rec;
                rec.x = (unsigned)t;
                rec.y = __float_as_uint(cur);
                uint2* addr = (fire && (n < LL)) ? (recp + n) : dump;
                *addr = rec;
                n += fire ? 1 : 0;
                I = fire ? (I - 1.0f) : I;
            }
            p = pn; q = qn;
        }
        g_nfires[b] = (n < LL) ? n : LL;
    }
}

// ---------------------------------------------------------------------------
// Kernel B: one CTA per output token (b,k). 128 threads x float4 covers H=512.
// out[b,k] = rem_{k-1} * h[pos_{k-1}]                        (boundary, k>0)
//          + sum_{t in (pos_{k-1}, pos_k)} (alpha_t*scale) * h[t]
//          + cur_k * h[pos_k]
// rem_{k-1} = alpha_{pos_{k-1}}*scale - cur_{k-1}  (bit-identical recompute).
// Depth-1 software pipeline (the R5 structure that hit 28.2us / 63.5% DRAM).
// ---------------------------------------------------------------------------
__global__ void __launch_bounds__(128)
cif_gather_kernel(const float* __restrict__ hidden,
                  const float* __restrict__ alphas,
                  float* __restrict__ out) {
    const int k = blockIdx.x;          // token
    const int b = blockIdx.y;          // batch
    const int tid = threadIdx.x;

    float4* o = (float4*)(out + ((size_t)b * LL + k) * HH) + tid;

    const int nf = g_nfires[b];
    if (k >= nf) {                     // unfired tokens are zero (out is poisoned)
        *o = make_float4(0.f, 0.f, 0.f, 0.f);
        return;
    }

    const float4* base = (const float4*)(hidden + (size_t)b * TT * HH);
    const float*  A    = alphas + (size_t)b * TT;
    const float   scale = g_scale[b];

    const uint2 rc = g_rec[b * LL + k];
    const int   t_end = (int)rc.x;
    const float cur_e = __uint_as_float(rc.y);

    float4 acc;
    int t0;
    if (k == 0) {
        acc = make_float4(0.f, 0.f, 0.f, 0.f);
        t0 = 0;
    } else {
        const uint2 rp = g_rec[b * LL + k - 1];
        const int   tp = (int)rp.x;
        const float cur_p = __uint_as_float(rp.y);
        const float a_p = A[tp] * scale;       // same FMUL as scan
        const float wr  = a_p - cur_p;         // remainds, bit-identical
        float4 h = base[(size_t)tp * (HH / 4) + tid];
        acc = make_float4(wr * h.x, wr * h.y, wr * h.z, wr * h.w);
        t0 = tp + 1;
    }

    // Depth-1 pipelined weighted accumulation over t in [t0, t_end].
    int t = t0;
    float4 h = base[(size_t)t * (HH / 4) + tid];
    float  wv = (t == t_end) ? cur_e : A[t] * scale;
    while (t < t_end) {
        float4 hn = base[(size_t)(t + 1) * (HH / 4) + tid];
        float  wn = (t + 1 == t_end) ? cur_e : A[t + 1] * scale;
        acc.x = fmaf(wv, h.x, acc.x);
        acc.y = fmaf(wv, h.y, acc.y);
        acc.z = fmaf(wv, h.z, acc.z);
        acc.w = fmaf(wv, h.w, acc.w);
        h = hn; wv = wn; ++t;
    }
    acc.x = fmaf(wv, h.x, acc.x);
    acc.y = fmaf(wv, h.y, acc.y);
    acc.z = fmaf(wv, h.z, acc.z);
    acc.w = fmaf(wv, h.w, acc.w);

    *o = acc;
}

extern "C" void kernel_launch(void* const* d_in, const int* in_sizes, int n_in,
                              void* d_out, int out_size) {
    const float* hidden = (const float*)d_in[0];
    const float* alphas = (const float*)d_in[1];
    const int*   tlen   = (const int*)d_in[2];
    float* out = (float*)d_out;

    cif_scan_kernel<<<1, 1024>>>(alphas, tlen);
    dim3 grid(LL, BB);
    cif_gather_kernel<<<grid, 128>>>(hidden, alphas, out);
}

// round 8
// speedup vs baseline: 1.2872x; 1.2872x over previous
#include <cuda_runtime.h>
#include <cstdint>

#define BB 32
#define TT 2000
#define HH 512
#define LL 256
#define THRESH 0.95f
#define NCHUNK 10
#define CHUNK  200          // TT / NCHUNK, divisible by 8

// Scratch (allocation-free rule: __device__ globals)
__device__ float g_w0[TT * BB];        // [t][b] per-frame "cur" weight
__device__ float g_rem[BB * LL];       // [b][k] remainder weight at k-th fire
__device__ int   g_fire_pos[BB * LL];  // [b][k] frame index of k-th fire
__device__ int   g_nfires[BB];

// ---------------------------------------------------------------------------
// Kernel A: 1 block, 1024 threads.
//  Phase 0: warp w sums alphas of batch w in fp64 -> per-batch scale.
//  Phase 1: warp 0, lane=batch, MINIMAL serial recurrence (no stores),
//           checkpointing (I, n) every CHUNK steps into shared.
//  Phase 2: warps 0..NCHUNK-1 replay chunk c from its checkpoint with full
//           bookkeeping (g_w0, fire records). Same fp32 op order as phase 1
//           => bit-identical fire decisions.
// ---------------------------------------------------------------------------
__global__ void __launch_bounds__(1024, 1)
cif_scan_kernel(const float* __restrict__ alphas, const int* __restrict__ tlen) {
    const int w    = threadIdx.x >> 5;
    const int lane = threadIdx.x & 31;
    __shared__ float s_scale[BB];
    __shared__ float s_I[NCHUNK][BB];
    __shared__ int   s_n[NCHUNK][BB];

    // Phase 0: fp64 correctly-rounded per-batch alpha sum (unchanged).
    double s = 0.0;
    const float* ap = alphas + w * TT;
    for (int t = lane; t < TT; t += 32) s += (double)ap[t];
    #pragma unroll
    for (int off = 16; off; off >>= 1) s += __shfl_down_sync(0xffffffffu, s, off);
    if (lane == 0) {
        float sumf = (float)s;                 // fp32 sum (closest to XLA's)
        s_scale[w] = (float)tlen[w] / sumf;    // ref: num / sum (fp32 div)
    }
    __syncthreads();

    // Phase 1: warp 0, lane = batch. Bare-bones chain: ~6 instr/iter.
    if (threadIdx.x < 32) {
        const int b = threadIdx.x;
        const float scale = s_scale[b];
        const float4* a4 = (const float4*)(alphas + b * TT);

        float I = 0.0f;
        int   n = 0;
        float4 p = a4[0];
        float4 q = a4[1];
        for (int c = 0; c < NCHUNK; ++c) {
            s_I[c][b] = I;
            s_n[c][b] = n;
            const int cbase = c * CHUNK;
            for (int t0 = 0; t0 < CHUNK; t0 += 8) {
                const int tg = cbase + t0;
                float4 pn, qn;
                if (tg + 8 < TT) {             // prefetch next 8 alphas
                    pn = a4[(tg >> 2) + 2];
                    qn = a4[(tg >> 2) + 3];
                }
                float ab[8] = {p.x, p.y, p.z, p.w, q.x, q.y, q.z, q.w};
                #pragma unroll
                for (int u = 0; u < 8; ++u) {
                    float a  = ab[u] * scale;  // ref: alphas * scale
                    float I2 = I + a;          // ref: integrate + alpha
                    bool fire = (I2 >= THRESH);
                    I = fire ? (I2 - 1.0f) : I2;
                    n += fire ? 1 : 0;
                }
                p = pn; q = qn;
            }
        }
        g_nfires[b] = (n < LL) ? n : LL;
    }
    __syncthreads();

    // Phase 2: warp c replays chunk c with full bookkeeping, lane = batch.
    if (w < NCHUNK) {
        const int b = lane;
        const int c = w;
        const float scale = s_scale[b];
        float I = s_I[c][b];
        int   n = s_n[c][b];
        const int tbase = c * CHUNK;
        // (b*TT + tbase) is a multiple of 4 -> float4-safe.
        const float4* a4 = (const float4*)(alphas + b * TT + tbase);

        float4 p = a4[0];
        float4 q = a4[1];
        for (int t0 = 0; t0 < CHUNK; t0 += 8) {
            float4 pn, qn;
            if (t0 + 8 < CHUNK) {
                pn = a4[(t0 >> 2) + 2];
                qn = a4[(t0 >> 2) + 3];
            }
            float ab[8] = {p.x, p.y, p.z, p.w, q.x, q.y, q.z, q.w};
            #pragma unroll
            for (int u = 0; u < 8; ++u) {
                const int t = tbase + t0 + u;
                float a = ab[u] * scale;       // identical ops -> identical I
                float d = 1.0f - I;            // dist_completion
                I = I + a;
                bool fire = (I >= THRESH);
                float cur = fire ? d : a;
                g_w0[t * BB + b] = cur;        // coalesced across lanes
                if (fire && (n < LL)) {
                    g_fire_pos[b * LL + n] = t;
                    g_rem[b * LL + n] = a - cur;   // remainds
                }
                n += fire ? 1 : 0;
                I = fire ? (I - 1.0f) : I;
            }
            p = pn; q = qn;
        }
    }
}

// ---------------------------------------------------------------------------
// Kernel B: exact R5 gather (28.2us / DRAM 63.5%). One CTA per token (b,k),
// 128 threads x float4 covers H=512.
// out[b,k] = rem_{k-1} * h[fire_{k-1}]                     (boundary, k>0)
//          + sum_{t in (fire_{k-1}, fire_k]} w0[t] * h[t]
// ---------------------------------------------------------------------------
__global__ void __launch_bounds__(128)
cif_gather_kernel(const float* __restrict__ hidden, float* __restrict__ out) {
    const int k = blockIdx.x;          // token
    const int b = blockIdx.y;          // batch
    const int tid = threadIdx.x;

    float4* o = (float4*)(out + ((size_t)b * LL + k) * HH) + tid;

    const int nf = g_nfires[b];
    if (k >= nf) {                     // unfired tokens are zero
        *o = make_float4(0.f, 0.f, 0.f, 0.f);
        return;
    }

    const float4* base = (const float4*)(hidden + (size_t)b * TT * HH);
    const int t_end = g_fire_pos[b * LL + k];

    float4 acc;
    int t0;
    if (k == 0) {
        acc = make_float4(0.f, 0.f, 0.f, 0.f);
        t0 = 0;
    } else {
        const int   tp = g_fire_pos[b * LL + k - 1];
        const float wr = g_rem[b * LL + k - 1];
        float4 h = base[(size_t)tp * (HH / 4) + tid];
        acc = make_float4(wr * h.x, wr * h.y, wr * h.z, wr * h.w);
        t0 = tp + 1;
    }

    // Depth-1 software pipeline: prefetch next row while fma'ing current.
    int t = t0;
    float4 h = base[(size_t)t * (HH / 4) + tid];
    float  wv = g_w0[t * BB + b];
    while (t < t_end) {
        float4 hn = base[(size_t)(t + 1) * (HH / 4) + tid];
        float  wn = g_w0[(t + 1) * BB + b];
        acc.x = fmaf(wv, h.x, acc.x);
        acc.y = fmaf(wv, h.y, acc.y);
        acc.z = fmaf(wv, h.z, acc.z);
        acc.w = fmaf(wv, h.w, acc.w);
        h = hn; wv = wn; ++t;
    }
    acc.x = fmaf(wv, h.x, acc.x);
    acc.y = fmaf(wv, h.y, acc.y);
    acc.z = fmaf(wv, h.z, acc.z);
    acc.w = fmaf(wv, h.w, acc.w);

    *o = acc;
}

extern "C" void kernel_launch(void* const* d_in, const int* in_sizes, int n_in,
                              void* d_out, int out_size) {
    const float* hidden = (const float*)d_in[0];
    const float* alphas = (const float*)d_in[1];
    const int*   tlen   = (const int*)d_in[2];
    float* out = (float*)d_out;

    cif_scan_kernel<<<1, 1024>>>(alphas, tlen);
    dim3 grid(LL, BB);
    cif_gather_kernel<<<grid, 128>>>(hidden, out);
}

// round 11
// speedup vs baseline: 1.4759x; 1.1466x over previous
#include <cuda_runtime.h>
#include <cstdint>

#define BB 32
#define TT 2000
#define HH 512
#define LL 256
#define THRESH 0.95f
#define CS   100            // staging chunk (smem)
#define NCS  20             // TT / CS
#define RCH  200            // replay chunk
#define NRCH 10             // TT / RCH

// Scratch (allocation-free rule: __device__ globals)
__device__ float g_w0[TT * BB];        // [t][b] per-frame "cur" weight
__device__ float g_rem[BB * LL];       // [b][k] remainder weight at k-th fire
__device__ int   g_fire_pos[BB * LL];  // [b][k] frame index of k-th fire
__device__ int   g_nfires[BB];

// ---------------------------------------------------------------------------
// Kernel A: 1 block, 1024 threads.
//  Phase 0: warp w sums alphas of batch w in fp64 -> per-batch scale.
//  Phase 1: double-buffered SMEM pipeline. Warps 1-31 stage scaled alphas
//           (a = alphas*scale, same FMUL as reference) for chunk c+1 while
//           warp 0 (lane = batch) runs the minimal serial recurrence on
//           chunk c from SMEM (LDS, 29-cyc fixed latency, conflict-free).
//           Checkpoints (I, n) every RCH steps.
//  Phase 2: warps 0..9 replay their RCH-chunk from the checkpoint with full
//           bookkeeping (g_w0, fire records). Same fp32 op order =>
//           bit-identical fire decisions.
// ---------------------------------------------------------------------------
__global__ void __launch_bounds__(1024, 1)
cif_scan_kernel(const float* __restrict__ alphas, const int* __restrict__ tlen) {
    const int w    = threadIdx.x >> 5;
    const int lane = threadIdx.x & 31;
    __shared__ float s_scale[BB];
    __shared__ float s_I[NRCH][BB];
    __shared__ int   s_n[NRCH][BB];
    __shared__ float s_a[2][CS * BB];      // [buf][t_local*32 + b]

    // Phase 0: fp64 correctly-rounded per-batch alpha sum (unchanged).
    double s = 0.0;
    const float* ap = alphas + w * TT;
    for (int t = lane; t < TT; t += 32) s += (double)ap[t];
    #pragma unroll
    for (int off = 16; off; off >>= 1) s += __shfl_down_sync(0xffffffffu, s, off);
    if (lane == 0) {
        float sumf = (float)s;                 // fp32 sum (closest to XLA's)
        s_scale[w] = (float)tlen[w] / sumf;    // ref: num / sum (fp32 div)
    }
    __syncthreads();

    // Prologue: everyone stages chunk 0 into buffer 0.
    {
        const int tid = threadIdx.x;
        for (int idx = tid; idx < CS * BB; idx += 1024) {
            const int b  = idx & 31;
            const int tl = idx >> 5;
            s_a[0][idx] = alphas[b * TT + tl] * s_scale[b];  // ref FMUL
        }
    }
    __syncthreads();

    // Phase 1 pipeline over NCS chunks.
    float I = 0.0f;                            // live only in warp 0
    int   n = 0;
    for (int c = 0; c < NCS; ++c) {
        if (w == 0) {
            const int b = lane;
            if ((c & 1) == 0) {                // checkpoint at t = c*CS (RCH-aligned)
                s_I[c >> 1][b] = I;
                s_n[c >> 1][b] = n;
            }
            const float* sa = s_a[c & 1] + b;
            #pragma unroll
            for (int t0 = 0; t0 < CS; t0 += 4) {
                float a0 = sa[(t0 + 0) * BB];
                float a1 = sa[(t0 + 1) * BB];
                float a2 = sa[(t0 + 2) * BB];
                float a3 = sa[(t0 + 3) * BB];
                float I2;
                I2 = I + a0; { bool f = (I2 >= THRESH); n += f ? 1 : 0; I = f ? (I2 - 1.0f) : I2; }
                I2 = I + a1; { bool f = (I2 >= THRESH); n += f ? 1 : 0; I = f ? (I2 - 1.0f) : I2; }
                I2 = I + a2; { bool f = (I2 >= THRESH); n += f ? 1 : 0; I = f ? (I2 - 1.0f) : I2; }
                I2 = I + a3; { bool f = (I2 >= THRESH); n += f ? 1 : 0; I = f ? (I2 - 1.0f) : I2; }
            }
        } else if (c + 1 < NCS) {
            // Warps 1-31 stage chunk c+1 into the other buffer.
            const int base_t = (c + 1) * CS;
            float* dst = s_a[(c + 1) & 1];
            for (int idx = threadIdx.x - 32; idx < CS * BB; idx += 992) {
                const int b  = idx & 31;
                const int tl = idx >> 5;
                dst[idx] = alphas[b * TT + base_t + tl] * s_scale[b];
            }
        }
        __syncthreads();
    }
    if (w == 0) {
        g_nfires[lane] = (n < LL) ? n : LL;
    }
    __syncthreads();

    // Phase 2: warp c replays RCH-chunk c with full bookkeeping, lane = batch.
    if (w < NRCH) {
        const int b = lane;
        const int c = w;
        const float scale = s_scale[b];
        float Ir = s_I[c][b];
        int   nr = s_n[c][b];
        const int tbase = c * RCH;
        // (b*TT + tbase) is a multiple of 4 -> float4-safe.
        const float4* a4 = (const float4*)(alphas + b * TT + tbase);

        float4 p = a4[0];
        float4 q = a4[1];
        for (int t0 = 0; t0 < RCH; t0 += 8) {
            float4 pn, qn;
            if (t0 + 8 < RCH) {
                pn = a4[(t0 >> 2) + 2];
                qn = a4[(t0 >> 2) + 3];
            }
            float ab[8] = {p.x, p.y, p.z, p.w, q.x, q.y, q.z, q.w};
            #pragma unroll
            for (int u = 0; u < 8; ++u) {
                const int t = tbase + t0 + u;
                float a = ab[u] * scale;       // identical ops -> identical I
                float d = 1.0f - Ir;           // dist_completion
                Ir = Ir + a;
                bool fire = (Ir >= THRESH);
                float cur = fire ? d : a;
                g_w0[t * BB + b] = cur;        // coalesced across lanes
                if (fire && (nr < LL)) {
                    g_fire_pos[b * LL + nr] = t;
                    g_rem[b * LL + nr] = a - cur;  // remainds
                }
                nr += fire ? 1 : 0;
                Ir = fire ? (Ir - 1.0f) : Ir;
            }
            p = pn; q = qn;
        }
    }
}

// ---------------------------------------------------------------------------
// Kernel B: exact R5/R8 gather (28-29us / DRAM ~62%). One CTA per token
// (b,k), 128 threads x float4 covers H=512.
// out[b,k] = rem_{k-1} * h[fire_{k-1}]                     (boundary, k>0)
//          + sum_{t in (fire_{k-1}, fire_k]} w0[t] * h[t]
// ---------------------------------------------------------------------------
__global__ void __launch_bounds__(128)
cif_gather_kernel(const float* __restrict__ hidden, float* __restrict__ out) {
    const int k = blockIdx.x;          // token
    const int b = blockIdx.y;          // batch
    const int tid = threadIdx.x;

    float4* o = (float4*)(out + ((size_t)b * LL + k) * HH) + tid;

    const int nf = g_nfires[b];
    if (k >= nf) {                     // unfired tokens are zero
        *o = make_float4(0.f, 0.f, 0.f, 0.f);
        return;
    }

    const float4* base = (const float4*)(hidden + (size_t)b * TT * HH);
    const int t_end = g_fire_pos[b * LL + k];

    float4 acc;
    int t0;
    if (k == 0) {
        acc = make_float4(0.f, 0.f, 0.f, 0.f);
        t0 = 0;
    } else {
        const int   tp = g_fire_pos[b * LL + k - 1];
        const float wr = g_rem[b * LL + k - 1];
        float4 h = base[(size_t)tp * (HH / 4) + tid];
        acc = make_float4(wr * h.x, wr * h.y, wr * h.z, wr * h.w);
        t0 = tp + 1;
    }

    // Depth-1 software pipeline: prefetch next row while fma'ing current.
    int t = t0;
    float4 h = base[(size_t)t * (HH / 4) + tid];
    float  wv = g_w0[t * BB + b];
    while (t < t_end) {
        float4 hn = base[(size_t)(t + 1) * (HH / 4) + tid];
        float  wn = g_w0[(t + 1) * BB + b];
        acc.x = fmaf(wv, h.x, acc.x);
        acc.y = fmaf(wv, h.y, acc.y);
        acc.z = fmaf(wv, h.z, acc.z);
        acc.w = fmaf(wv, h.w, acc.w);
        h = hn; wv = wn; ++t;
    }
    acc.x = fmaf(wv, h.x, acc.x);
    acc.y = fmaf(wv, h.y, acc.y);
    acc.z = fmaf(wv, h.z, acc.z);
    acc.w = fmaf(wv, h.w, acc.w);

    *o = acc;
}

extern "C" void kernel_launch(void* const* d_in, const int* in_sizes, int n_in,
                              void* d_out, int out_size) {
    const float* hidden = (const float*)d_in[0];
    const float* alphas = (const float*)d_in[1];
    const int*   tlen   = (const int*)d_in[2];
    float* out = (float*)d_out;

    cif_scan_kernel<<<1, 1024>>>(alphas, tlen);
    dim3 grid(LL, BB);
    cif_gather_kernel<<<grid, 128>>>(hidden, out);
}